// round 1
// baseline (speedup 1.0000x reference)
#include <cuda_runtime.h>
#include <math.h>

// Problem constants
#define NB   4
#define SEQ  2048
#define DM   1024
#define NH   16
#define HD   64
#define MROWS (NB*SEQ)          // 8192

// Scratch (device globals — no allocation allowed)
__device__ float g_q  [MROWS*DM];
__device__ float g_k  [MROWS*DM];
__device__ float g_v  [MROWS*DM];
__device__ float g_att[MROWS*DM];

// ---------------------------------------------------------------------------
// GEMM: C[M,1024] = A[M,1024] @ W[1024,1024] + bias[1024]
// 128x128 tile, K-tile 8, 256 threads, 8x8 per thread (2x2 groups of 4x4).
// ---------------------------------------------------------------------------
__global__ __launch_bounds__(256) void gemm_bias_k(
    const float* __restrict__ A, const float* __restrict__ W,
    const float* __restrict__ bias, float* __restrict__ C)
{
    __shared__ float As[8][128];   // As[k][m]  (A transposed tile)
    __shared__ float Bs[8][128];   // Bs[k][n]

    const int t  = threadIdx.x;
    const int bm = blockIdx.y;     // 64 tiles of M
    const int bn = blockIdx.x;     // 8 tiles of N
    const int tr = t >> 4;         // 0..15
    const int tc = t & 15;         // 0..15

    float acc[8][8];
    #pragma unroll
    for (int i = 0; i < 8; i++)
        #pragma unroll
        for (int j = 0; j < 8; j++) acc[i][j] = 0.f;

    const int arow = t >> 1;           // 0..127
    const int ak4  = (t & 1) << 2;     // 0 or 4
    const int wrow = t >> 5;           // 0..7
    const int wc4  = (t & 31) << 2;    // 0..124

    const float* Ap = A + (bm * 128 + arow) * DM + ak4;
    const float* Wp = W + wrow * DM + bn * 128 + wc4;

    for (int kt = 0; kt < 1024; kt += 8) {
        float4 av = *(const float4*)(Ap + kt);
        float4 wv = *(const float4*)(Wp + kt * DM);
        As[ak4 + 0][arow] = av.x;
        As[ak4 + 1][arow] = av.y;
        As[ak4 + 2][arow] = av.z;
        As[ak4 + 3][arow] = av.w;
        *(float4*)&Bs[wrow][wc4] = wv;
        __syncthreads();

        #pragma unroll
        for (int kk = 0; kk < 8; kk++) {
            float4 a0 = *(const float4*)&As[kk][tr * 4];
            float4 a1 = *(const float4*)&As[kk][64 + tr * 4];
            float4 b0 = *(const float4*)&Bs[kk][tc * 4];
            float4 b1 = *(const float4*)&Bs[kk][64 + tc * 4];
            float a[8] = {a0.x, a0.y, a0.z, a0.w, a1.x, a1.y, a1.z, a1.w};
            float bb[8] = {b0.x, b0.y, b0.z, b0.w, b1.x, b1.y, b1.z, b1.w};
            #pragma unroll
            for (int i = 0; i < 8; i++)
                #pragma unroll
                for (int j = 0; j < 8; j++)
                    acc[i][j] += a[i] * bb[j];
        }
        __syncthreads();
    }

    // Epilogue: add bias, write float4s
    #pragma unroll
    for (int jg = 0; jg < 2; jg++) {
        const int c = bn * 128 + jg * 64 + tc * 4;
        float4 bv = *(const float4*)(bias + c);
        #pragma unroll
        for (int ig = 0; ig < 2; ig++) {
            #pragma unroll
            for (int ii = 0; ii < 4; ii++) {
                const int r = bm * 128 + ig * 64 + tr * 4 + ii;
                const int i = ig * 4 + ii;
                float4 ov;
                ov.x = acc[i][jg * 4 + 0] + bv.x;
                ov.y = acc[i][jg * 4 + 1] + bv.y;
                ov.z = acc[i][jg * 4 + 2] + bv.z;
                ov.w = acc[i][jg * 4 + 3] + bv.w;
                *(float4*)(C + r * DM + c) = ov;
            }
        }
    }
}

// ---------------------------------------------------------------------------
// Flash-style attention, fp32.
// Block: (b*16+h, q-tile of 64 rows). 256 threads: tr=t>>4 -> q rows tr+16i,
// tc=t&15 -> k cols / d cols tc+16j. 64-key chunks, online softmax.
// Smem: Qs[64][64] + KPs[64][64] (K tile, then reused for P) + Vs[64][64]
//       = 48 KB exactly. K tile stored with float4-group XOR swizzle so that
//       the 16-lane strided row reads are bank-conflict-free.
// ---------------------------------------------------------------------------
__global__ __launch_bounds__(256) void attn_k(
    const float* __restrict__ q, const float* __restrict__ k,
    const float* __restrict__ v, const int* __restrict__ mask,
    float* __restrict__ o)
{
    __shared__ float Qs [64 * 64];
    __shared__ float KPs[64 * 64];
    __shared__ float Vs [64 * 64];

    const int t  = threadIdx.x;
    const int tr = t >> 4;
    const int tc = t & 15;
    const int bh = blockIdx.x;
    const int b  = bh >> 4;
    const int h  = bh & 15;
    const int qt = blockIdx.y;

    const int qbase = b * SEQ + qt * 64;   // global row of first q in tile
    const int kbase = b * SEQ;
    const int hcol  = h * HD;

    // Load Q tile (natural layout)
    #pragma unroll
    for (int it = 0; it < 4; it++) {
        int idx = it * 256 + t;
        int r = idx >> 4, c4 = (idx & 15) << 2;
        float4 qv = *(const float4*)(q + (qbase + r) * DM + hcol + c4);
        *(float4*)&Qs[r * 64 + c4] = qv;
    }

    float m[4], l[4], oacc[4][4];
    #pragma unroll
    for (int i = 0; i < 4; i++) {
        m[i] = -1e30f; l[i] = 0.f;
        #pragma unroll
        for (int j = 0; j < 4; j++) oacc[i][j] = 0.f;
    }

    for (int kt = 0; kt < SEQ / 64; kt++) {
        __syncthreads();   // prev PV reads done (and Q tile visible on iter 0)

        // Load K (swizzled) and V tiles for this 64-key chunk
        #pragma unroll
        for (int it = 0; it < 4; it++) {
            int idx = it * 256 + t;
            int r = idx >> 4, c4 = (idx & 15) << 2;
            const int grow = (kbase + kt * 64 + r) * DM + hcol + c4;
            float4 kv4 = *(const float4*)(k + grow);
            float4 vv4 = *(const float4*)(v + grow);
            int sc = (((c4 >> 2) ^ (r & 15)) << 2);
            *(float4*)&KPs[r * 64 + sc] = kv4;
            *(float4*)&Vs [r * 64 + c4] = vv4;
        }
        __syncthreads();

        // S = Q K^T  (s[i][j] : q row tr+16i, k col tc+16j)
        float s[4][4];
        #pragma unroll
        for (int i = 0; i < 4; i++)
            #pragma unroll
            for (int j = 0; j < 4; j++) s[i][j] = 0.f;

        #pragma unroll 4
        for (int d4 = 0; d4 < 64; d4 += 4) {
            float4 qv[4], kv[4];
            #pragma unroll
            for (int i = 0; i < 4; i++)
                qv[i] = *(const float4*)&Qs[(tr + 16 * i) * 64 + d4];
            const int scol = (((d4 >> 2) ^ tc) << 2);   // kr&15 == tc for all j
            #pragma unroll
            for (int j = 0; j < 4; j++)
                kv[j] = *(const float4*)&KPs[(tc + 16 * j) * 64 + scol];
            #pragma unroll
            for (int i = 0; i < 4; i++)
                #pragma unroll
                for (int j = 0; j < 4; j++)
                    s[i][j] += qv[i].x * kv[j].x + qv[i].y * kv[j].y
                             + qv[i].z * kv[j].z + qv[i].w * kv[j].w;
        }
        __syncthreads();   // all K reads done before P overwrites KPs

        // Mask + online softmax; write P into KPs
        int mv[4];
        #pragma unroll
        for (int j = 0; j < 4; j++)
            mv[j] = mask[b * SEQ + kt * 64 + tc + 16 * j];

        #pragma unroll
        for (int i = 0; i < 4; i++) {
            float rm = -1e30f;
            #pragma unroll
            for (int j = 0; j < 4; j++) {
                s[i][j] *= 0.125f;               // 1/sqrt(64)
                if (mv[j] == 0) s[i][j] = -1e30f;
                rm = fmaxf(rm, s[i][j]);
            }
            #pragma unroll
            for (int off = 8; off; off >>= 1)
                rm = fmaxf(rm, __shfl_xor_sync(0xffffffffu, rm, off));
            float mn    = fmaxf(m[i], rm);
            float alpha = __expf(m[i] - mn);
            float rs = 0.f;
            float p[4];
            #pragma unroll
            for (int j = 0; j < 4; j++) {
                p[j] = mv[j] ? __expf(s[i][j] - mn) : 0.f;
                rs += p[j];
            }
            #pragma unroll
            for (int off = 8; off; off >>= 1)
                rs += __shfl_xor_sync(0xffffffffu, rs, off);
            l[i] = l[i] * alpha + rs;
            m[i] = mn;
            #pragma unroll
            for (int j = 0; j < 4; j++) oacc[i][j] *= alpha;
            #pragma unroll
            for (int j = 0; j < 4; j++)
                KPs[(tr + 16 * i) * 64 + tc + 16 * j] = p[j];
        }
        __syncthreads();   // P visible to all

        // O += P @ V   (oacc[i][j] : q row tr+16i, d col tc+16j)
        #pragma unroll 4
        for (int k4 = 0; k4 < 64; k4 += 4) {
            float pr[4][4];
            #pragma unroll
            for (int i = 0; i < 4; i++) {
                float4 p4 = *(const float4*)&KPs[(tr + 16 * i) * 64 + k4];
                pr[i][0] = p4.x; pr[i][1] = p4.y; pr[i][2] = p4.z; pr[i][3] = p4.w;
            }
            #pragma unroll
            for (int kk = 0; kk < 4; kk++) {
                float vv[4];
                #pragma unroll
                for (int j = 0; j < 4; j++)
                    vv[j] = Vs[(k4 + kk) * 64 + tc + 16 * j];
                #pragma unroll
                for (int i = 0; i < 4; i++)
                    #pragma unroll
                    for (int j = 0; j < 4; j++)
                        oacc[i][j] += pr[i][kk] * vv[j];
            }
        }
    }

    // Finalize and write attention output
    #pragma unroll
    for (int i = 0; i < 4; i++) {
        float inv = (l[i] > 0.f) ? 1.f / l[i] : 0.f;
        const int gr = qbase + tr + 16 * i;
        #pragma unroll
        for (int j = 0; j < 4; j++)
            o[gr * DM + hcol + tc + 16 * j] = oacc[i][j] * inv;
    }
}

// ---------------------------------------------------------------------------
// Launch: 3 projections -> attention -> output projection. All on the default
// stream (sequential, graph-capturable, no sync / no alloc).
// ---------------------------------------------------------------------------
extern "C" void kernel_launch(void* const* d_in, const int* in_sizes, int n_in,
                              void* d_out, int out_size)
{
    const float* Q    = (const float*)d_in[0];
    const float* K    = (const float*)d_in[1];
    const float* V    = (const float*)d_in[2];
    const int*   mask = (const int*)  d_in[3];
    const float* Wq   = (const float*)d_in[4];
    const float* bq   = (const float*)d_in[5];
    const float* Wk   = (const float*)d_in[6];
    const float* bk   = (const float*)d_in[7];
    const float* Wv   = (const float*)d_in[8];
    const float* bv   = (const float*)d_in[9];
    const float* Wo   = (const float*)d_in[10];
    const float* bo   = (const float*)d_in[11];
    float* out = (float*)d_out;

    float *gq, *gk, *gv, *ga;
    cudaGetSymbolAddress((void**)&gq, g_q);
    cudaGetSymbolAddress((void**)&gk, g_k);
    cudaGetSymbolAddress((void**)&gv, g_v);
    cudaGetSymbolAddress((void**)&ga, g_att);

    dim3 gemm_grid(DM / 128, MROWS / 128);   // (8, 64)
    dim3 attn_grid(NB * NH, SEQ / 64);       // (64, 32)

    gemm_bias_k<<<gemm_grid, 256>>>(Q, Wq, bq, gq);
    gemm_bias_k<<<gemm_grid, 256>>>(K, Wk, bk, gk);
    gemm_bias_k<<<gemm_grid, 256>>>(V, Wv, bv, gv);
    attn_k<<<attn_grid, 256>>>(gq, gk, gv, mask, ga);
    gemm_bias_k<<<gemm_grid, 256>>>(ga, Wo, bo, out);
}

// round 3
// speedup vs baseline: 1.4238x; 1.4238x over previous
#include <cuda_runtime.h>
#include <math.h>
#include <stdint.h>

// Problem constants
#define NB   4
#define SEQ  2048
#define DM   1024
#define NH   16
#define HD   64
#define MROWS (NB*SEQ)          // 8192

// Scratch (device globals — no allocation allowed)
__device__ float g_q  [MROWS*DM];
__device__ float g_k  [MROWS*DM];
__device__ float g_v  [MROWS*DM];
__device__ float g_att[MROWS*DM];
__device__ float g_wt [4][DM*DM];   // transposed weights Wt[n][k] = W[k][n]

__device__ __forceinline__ uint32_t tf32r(float x) {
    uint32_t u;
    asm("cvt.rna.tf32.f32 %0, %1;" : "=r"(u) : "f"(x));
    return u;
}

#define MMA_TF32(c0, c1, c2, c3, a0, a1, a2, a3, b0, b1) \
    asm volatile("mma.sync.aligned.m16n8k8.row.col.f32.tf32.tf32.f32 " \
        "{%0,%1,%2,%3}, {%4,%5,%6,%7}, {%8,%9}, {%0,%1,%2,%3};" \
        : "+f"(c0), "+f"(c1), "+f"(c2), "+f"(c3) \
        : "r"(a0), "r"(a1), "r"(a2), "r"(a3), "r"(b0), "r"(b1))

// ---------------------------------------------------------------------------
// Weight transpose: D[n*1024+k] = S[k*1024+n]
// ---------------------------------------------------------------------------
__global__ __launch_bounds__(256) void transpose_k(
    const float* __restrict__ S, float* __restrict__ D)
{
    __shared__ float tile[32][33];
    const int tx = threadIdx.x, ty = threadIdx.y;
    const int x = blockIdx.x * 32 + tx;
    #pragma unroll
    for (int j = ty; j < 32; j += 8)
        tile[j][tx] = S[(size_t)(blockIdx.y * 32 + j) * DM + x];
    __syncthreads();
    const int x2 = blockIdx.y * 32 + tx;
    #pragma unroll
    for (int j = ty; j < 32; j += 8)
        D[(size_t)(blockIdx.x * 32 + j) * DM + x2] = tile[tx][j];
}

// ---------------------------------------------------------------------------
// Tensor-core GEMM via mma.sync (tf32):
//   C[M,1024] = A[M,1024] @ W + bias, weights given pre-transposed Wt[n][k].
// CTA: 128x128 tile, BK=32 chunks, 256 threads = 8 warps (4m x 2n),
// warp computes 32x64 with 2x8 m16n8k8 tiles. Register-prefetch double buffer.
// SMEM [row][32+4pad] -> conflict-free fragment gathers.
// ---------------------------------------------------------------------------
#define LDW 36   // padded row stride in words

__global__ __launch_bounds__(256) void gemm_mma_k(
    const float* __restrict__ A, const float* __restrict__ Wt,
    const float* __restrict__ bias, float* __restrict__ C)
{
    __shared__ uint32_t As[128 * LDW];
    __shared__ uint32_t Bs[128 * LDW];

    const int t    = threadIdx.x;
    const int lane = t & 31;
    const int wid  = t >> 5;
    const int m0   = blockIdx.y * 128;
    const int n0   = blockIdx.x * 128;
    const int wm   = (wid & 3) * 32;    // warp m offset in tile
    const int wn   = (wid >> 2) * 64;   // warp n offset in tile
    const int g    = lane >> 2;         // fragment group row 0..7
    const int kq   = lane & 3;          // fragment k quad 0..3

    // Global-load addressing: idx = i*256+t -> r=idx>>3 (0..127), c4=(idx&7)*4
    const int lr  = t >> 3;             // row for i=0 (stride 32 rows per i)
    const int lc4 = (t & 7) << 2;       // k-col (float)

    float acc[2][8][4];
    #pragma unroll
    for (int mi = 0; mi < 2; mi++)
        #pragma unroll
        for (int nj = 0; nj < 8; nj++)
            #pragma unroll
            for (int r = 0; r < 4; r++) acc[mi][nj][r] = 0.f;

    float4 pa[4], pb[4];

    // Prefetch chunk 0
    #pragma unroll
    for (int i = 0; i < 4; i++) {
        pa[i] = *(const float4*)(A  + (size_t)(m0 + lr + i * 32) * DM + lc4);
        pb[i] = *(const float4*)(Wt + (size_t)(n0 + lr + i * 32) * DM + lc4);
    }

    #pragma unroll 1
    for (int kt = 0; kt < 32; kt++) {
        // Store prefetched chunk into smem (tf32-rounded)
        #pragma unroll
        for (int i = 0; i < 4; i++) {
            uint32_t* ap = &As[(lr + i * 32) * LDW + lc4];
            uint32_t* bp = &Bs[(lr + i * 32) * LDW + lc4];
            ap[0] = tf32r(pa[i].x); ap[1] = tf32r(pa[i].y);
            ap[2] = tf32r(pa[i].z); ap[3] = tf32r(pa[i].w);
            bp[0] = tf32r(pb[i].x); bp[1] = tf32r(pb[i].y);
            bp[2] = tf32r(pb[i].z); bp[3] = tf32r(pb[i].w);
        }
        __syncthreads();

        // Prefetch next chunk (global) while computing this one
        if (kt + 1 < 32) {
            const int kf = (kt + 1) * 32 + lc4;
            #pragma unroll
            for (int i = 0; i < 4; i++) {
                pa[i] = *(const float4*)(A  + (size_t)(m0 + lr + i * 32) * DM + kf);
                pb[i] = *(const float4*)(Wt + (size_t)(n0 + lr + i * 32) * DM + kf);
            }
        }

        // 4 k-steps of m16n8k8
        #pragma unroll
        for (int ks = 0; ks < 4; ks++) {
            const int k0 = ks * 8 + kq;
            uint32_t af[2][4];
            #pragma unroll
            for (int mi = 0; mi < 2; mi++) {
                const int row = wm + mi * 16 + g;
                af[mi][0] = As[row * LDW + k0];
                af[mi][1] = As[(row + 8) * LDW + k0];
                af[mi][2] = As[row * LDW + k0 + 4];
                af[mi][3] = As[(row + 8) * LDW + k0 + 4];
            }
            #pragma unroll
            for (int nj = 0; nj < 8; nj++) {
                const int col = wn + nj * 8 + g;
                uint32_t b0 = Bs[col * LDW + k0];
                uint32_t b1 = Bs[col * LDW + k0 + 4];
                #pragma unroll
                for (int mi = 0; mi < 2; mi++)
                    MMA_TF32(acc[mi][nj][0], acc[mi][nj][1],
                             acc[mi][nj][2], acc[mi][nj][3],
                             af[mi][0], af[mi][1], af[mi][2], af[mi][3],
                             b0, b1);
            }
        }
        __syncthreads();
    }

    // Epilogue: c0,c1 -> (row=g, col=2*kq{+1}); c2,c3 -> row+8.
    #pragma unroll
    for (int mi = 0; mi < 2; mi++) {
        const int row = m0 + wm + mi * 16 + g;
        #pragma unroll
        for (int nj = 0; nj < 8; nj++) {
            const int col = n0 + wn + nj * 8 + kq * 2;
            const float bx = bias[col], by = bias[col + 1];
            float2 v0 = make_float2(acc[mi][nj][0] + bx, acc[mi][nj][1] + by);
            float2 v1 = make_float2(acc[mi][nj][2] + bx, acc[mi][nj][3] + by);
            *(float2*)(C + (size_t)row * DM + col)       = v0;
            *(float2*)(C + (size_t)(row + 8) * DM + col) = v1;
        }
    }
}

// ---------------------------------------------------------------------------
// Flash-style attention, fp32 (unchanged).
// ---------------------------------------------------------------------------
__global__ __launch_bounds__(256) void attn_k(
    const float* __restrict__ q, const float* __restrict__ k,
    const float* __restrict__ v, const int* __restrict__ mask,
    float* __restrict__ o)
{
    __shared__ float Qs [64 * 64];
    __shared__ float KPs[64 * 64];
    __shared__ float Vs [64 * 64];

    const int t  = threadIdx.x;
    const int tr = t >> 4;
    const int tc = t & 15;
    const int bh = blockIdx.x;
    const int b  = bh >> 4;
    const int h  = bh & 15;
    const int qt = blockIdx.y;

    const int qbase = b * SEQ + qt * 64;
    const int kbase = b * SEQ;
    const int hcol  = h * HD;

    #pragma unroll
    for (int it = 0; it < 4; it++) {
        int idx = it * 256 + t;
        int r = idx >> 4, c4 = (idx & 15) << 2;
        float4 qv = *(const float4*)(q + (qbase + r) * DM + hcol + c4);
        *(float4*)&Qs[r * 64 + c4] = qv;
    }

    float m[4], l[4], oacc[4][4];
    #pragma unroll
    for (int i = 0; i < 4; i++) {
        m[i] = -1e30f; l[i] = 0.f;
        #pragma unroll
        for (int j = 0; j < 4; j++) oacc[i][j] = 0.f;
    }

    for (int kt = 0; kt < SEQ / 64; kt++) {
        __syncthreads();

        #pragma unroll
        for (int it = 0; it < 4; it++) {
            int idx = it * 256 + t;
            int r = idx >> 4, c4 = (idx & 15) << 2;
            const int grow = (kbase + kt * 64 + r) * DM + hcol + c4;
            float4 kv4 = *(const float4*)(k + grow);
            float4 vv4 = *(const float4*)(v + grow);
            int sc = (((c4 >> 2) ^ (r & 15)) << 2);
            *(float4*)&KPs[r * 64 + sc] = kv4;
            *(float4*)&Vs [r * 64 + c4] = vv4;
        }
        __syncthreads();

        float s[4][4];
        #pragma unroll
        for (int i = 0; i < 4; i++)
            #pragma unroll
            for (int j = 0; j < 4; j++) s[i][j] = 0.f;

        #pragma unroll 4
        for (int d4 = 0; d4 < 64; d4 += 4) {
            float4 qv[4], kv[4];
            #pragma unroll
            for (int i = 0; i < 4; i++)
                qv[i] = *(const float4*)&Qs[(tr + 16 * i) * 64 + d4];
            const int scol = (((d4 >> 2) ^ tc) << 2);
            #pragma unroll
            for (int j = 0; j < 4; j++)
                kv[j] = *(const float4*)&KPs[(tc + 16 * j) * 64 + scol];
            #pragma unroll
            for (int i = 0; i < 4; i++)
                #pragma unroll
                for (int j = 0; j < 4; j++)
                    s[i][j] += qv[i].x * kv[j].x + qv[i].y * kv[j].y
                             + qv[i].z * kv[j].z + qv[i].w * kv[j].w;
        }
        __syncthreads();

        int mv[4];
        #pragma unroll
        for (int j = 0; j < 4; j++)
            mv[j] = mask[b * SEQ + kt * 64 + tc + 16 * j];

        #pragma unroll
        for (int i = 0; i < 4; i++) {
            float rm = -1e30f;
            #pragma unroll
            for (int j = 0; j < 4; j++) {
                s[i][j] *= 0.125f;
                if (mv[j] == 0) s[i][j] = -1e30f;
                rm = fmaxf(rm, s[i][j]);
            }
            #pragma unroll
            for (int off = 8; off; off >>= 1)
                rm = fmaxf(rm, __shfl_xor_sync(0xffffffffu, rm, off));
            float mn    = fmaxf(m[i], rm);
            float alpha = __expf(m[i] - mn);
            float rs = 0.f;
            float p[4];
            #pragma unroll
            for (int j = 0; j < 4; j++) {
                p[j] = mv[j] ? __expf(s[i][j] - mn) : 0.f;
                rs += p[j];
            }
            #pragma unroll
            for (int off = 8; off; off >>= 1)
                rs += __shfl_xor_sync(0xffffffffu, rs, off);
            l[i] = l[i] * alpha + rs;
            m[i] = mn;
            #pragma unroll
            for (int j = 0; j < 4; j++) oacc[i][j] *= alpha;
            #pragma unroll
            for (int j = 0; j < 4; j++)
                KPs[(tr + 16 * i) * 64 + tc + 16 * j] = p[j];
        }
        __syncthreads();

        #pragma unroll 4
        for (int k4 = 0; k4 < 64; k4 += 4) {
            float pr[4][4];
            #pragma unroll
            for (int i = 0; i < 4; i++) {
                float4 p4 = *(const float4*)&KPs[(tr + 16 * i) * 64 + k4];
                pr[i][0] = p4.x; pr[i][1] = p4.y; pr[i][2] = p4.z; pr[i][3] = p4.w;
            }
            #pragma unroll
            for (int kk = 0; kk < 4; kk++) {
                float vv[4];
                #pragma unroll
                for (int j = 0; j < 4; j++)
                    vv[j] = Vs[(k4 + kk) * 64 + tc + 16 * j];
                #pragma unroll
                for (int i = 0; i < 4; i++)
                    #pragma unroll
                    for (int j = 0; j < 4; j++)
                        oacc[i][j] += pr[i][kk] * vv[j];
            }
        }
    }

    #pragma unroll
    for (int i = 0; i < 4; i++) {
        float inv = (l[i] > 0.f) ? 1.f / l[i] : 0.f;
        const int gr = qbase + tr + 16 * i;
        #pragma unroll
        for (int j = 0; j < 4; j++)
            o[gr * DM + hcol + tc + 16 * j] = oacc[i][j] * inv;
    }
}

// ---------------------------------------------------------------------------
// Launch
// ---------------------------------------------------------------------------
extern "C" void kernel_launch(void* const* d_in, const int* in_sizes, int n_in,
                              void* d_out, int out_size)
{
    const float* Q    = (const float*)d_in[0];
    const float* K    = (const float*)d_in[1];
    const float* V    = (const float*)d_in[2];
    const int*   mask = (const int*)  d_in[3];
    const float* Wq   = (const float*)d_in[4];
    const float* bq   = (const float*)d_in[5];
    const float* Wk   = (const float*)d_in[6];
    const float* bk   = (const float*)d_in[7];
    const float* Wv   = (const float*)d_in[8];
    const float* bv   = (const float*)d_in[9];
    const float* Wo   = (const float*)d_in[10];
    const float* bo   = (const float*)d_in[11];
    float* out = (float*)d_out;

    float *gq, *gk, *gv, *ga, *gwt;
    cudaGetSymbolAddress((void**)&gq,  g_q);
    cudaGetSymbolAddress((void**)&gk,  g_k);
    cudaGetSymbolAddress((void**)&gv,  g_v);
    cudaGetSymbolAddress((void**)&ga,  g_att);
    cudaGetSymbolAddress((void**)&gwt, g_wt);
    float* wtq = gwt + 0 * (size_t)DM * DM;
    float* wtk = gwt + 1 * (size_t)DM * DM;
    float* wtv = gwt + 2 * (size_t)DM * DM;
    float* wto = gwt + 3 * (size_t)DM * DM;

    dim3 tgrid(DM / 32, DM / 32);            // (32, 32)
    dim3 tblk(32, 8);
    transpose_k<<<tgrid, tblk>>>(Wq, wtq);
    transpose_k<<<tgrid, tblk>>>(Wk, wtk);
    transpose_k<<<tgrid, tblk>>>(Wv, wtv);
    transpose_k<<<tgrid, tblk>>>(Wo, wto);

    dim3 gemm_grid(DM / 128, MROWS / 128);   // (8, 64)
    dim3 attn_grid(NB * NH, SEQ / 64);       // (64, 32)

    gemm_mma_k<<<gemm_grid, 256>>>(Q, wtq, bq, gq);
    gemm_mma_k<<<gemm_grid, 256>>>(K, wtk, bk, gk);
    gemm_mma_k<<<gemm_grid, 256>>>(V, wtv, bv, gv);
    attn_k<<<attn_grid, 256>>>(gq, gk, gv, mask, ga);
    gemm_mma_k<<<gemm_grid, 256>>>(ga, wto, bo, out);
}

// round 4
// speedup vs baseline: 3.1120x; 2.1857x over previous
#include <cuda_runtime.h>
#include <math.h>
#include <stdint.h>

// Problem constants
#define NB   4
#define SEQ  2048
#define DM   1024
#define NH   16
#define HD   64
#define MROWS (NB*SEQ)          // 8192

// Scratch (device globals — no allocation allowed)
__device__ float g_q  [MROWS*DM];
__device__ float g_k  [MROWS*DM];
__device__ float g_v  [MROWS*DM];
__device__ float g_att[MROWS*DM];
__device__ float g_wt [4][DM*DM];   // transposed weights Wt[n][k] = W[k][n]

__device__ __forceinline__ uint32_t tf32r(float x) {
    uint32_t u;
    asm("cvt.rna.tf32.f32 %0, %1;" : "=r"(u) : "f"(x));
    return u;
}

#define MMA_TF32(c0, c1, c2, c3, a0, a1, a2, a3, b0, b1) \
    asm volatile("mma.sync.aligned.m16n8k8.row.col.f32.tf32.tf32.f32 " \
        "{%0,%1,%2,%3}, {%4,%5,%6,%7}, {%8,%9}, {%0,%1,%2,%3};" \
        : "+f"(c0), "+f"(c1), "+f"(c2), "+f"(c3) \
        : "r"(a0), "r"(a1), "r"(a2), "r"(a3), "r"(b0), "r"(b1))

// ---------------------------------------------------------------------------
// Weight transpose: D[n*1024+k] = S[k*1024+n]
// ---------------------------------------------------------------------------
__global__ __launch_bounds__(256) void transpose_k(
    const float* __restrict__ S, float* __restrict__ D)
{
    __shared__ float tile[32][33];
    const int tx = threadIdx.x, ty = threadIdx.y;
    const int x = blockIdx.x * 32 + tx;
    #pragma unroll
    for (int j = ty; j < 32; j += 8)
        tile[j][tx] = S[(size_t)(blockIdx.y * 32 + j) * DM + x];
    __syncthreads();
    const int x2 = blockIdx.y * 32 + tx;
    #pragma unroll
    for (int j = ty; j < 32; j += 8)
        D[(size_t)(blockIdx.x * 32 + j) * DM + x2] = tile[tx][j];
}

// ---------------------------------------------------------------------------
// Tensor-core GEMM via mma.sync (tf32) — unchanged from R3 (passing).
// ---------------------------------------------------------------------------
#define LDW 36   // padded row stride in words

__global__ __launch_bounds__(256) void gemm_mma_k(
    const float* __restrict__ A, const float* __restrict__ Wt,
    const float* __restrict__ bias, float* __restrict__ C)
{
    __shared__ uint32_t As[128 * LDW];
    __shared__ uint32_t Bs[128 * LDW];

    const int t    = threadIdx.x;
    const int lane = t & 31;
    const int wid  = t >> 5;
    const int m0   = blockIdx.y * 128;
    const int n0   = blockIdx.x * 128;
    const int wm   = (wid & 3) * 32;
    const int wn   = (wid >> 2) * 64;
    const int g    = lane >> 2;
    const int kq   = lane & 3;

    const int lr  = t >> 3;
    const int lc4 = (t & 7) << 2;

    float acc[2][8][4];
    #pragma unroll
    for (int mi = 0; mi < 2; mi++)
        #pragma unroll
        for (int nj = 0; nj < 8; nj++)
            #pragma unroll
            for (int r = 0; r < 4; r++) acc[mi][nj][r] = 0.f;

    float4 pa[4], pb[4];

    #pragma unroll
    for (int i = 0; i < 4; i++) {
        pa[i] = *(const float4*)(A  + (size_t)(m0 + lr + i * 32) * DM + lc4);
        pb[i] = *(const float4*)(Wt + (size_t)(n0 + lr + i * 32) * DM + lc4);
    }

    #pragma unroll 1
    for (int kt = 0; kt < 32; kt++) {
        #pragma unroll
        for (int i = 0; i < 4; i++) {
            uint32_t* ap = &As[(lr + i * 32) * LDW + lc4];
            uint32_t* bp = &Bs[(lr + i * 32) * LDW + lc4];
            ap[0] = tf32r(pa[i].x); ap[1] = tf32r(pa[i].y);
            ap[2] = tf32r(pa[i].z); ap[3] = tf32r(pa[i].w);
            bp[0] = tf32r(pb[i].x); bp[1] = tf32r(pb[i].y);
            bp[2] = tf32r(pb[i].z); bp[3] = tf32r(pb[i].w);
        }
        __syncthreads();

        if (kt + 1 < 32) {
            const int kf = (kt + 1) * 32 + lc4;
            #pragma unroll
            for (int i = 0; i < 4; i++) {
                pa[i] = *(const float4*)(A  + (size_t)(m0 + lr + i * 32) * DM + kf);
                pb[i] = *(const float4*)(Wt + (size_t)(n0 + lr + i * 32) * DM + kf);
            }
        }

        #pragma unroll
        for (int ks = 0; ks < 4; ks++) {
            const int k0 = ks * 8 + kq;
            uint32_t af[2][4];
            #pragma unroll
            for (int mi = 0; mi < 2; mi++) {
                const int row = wm + mi * 16 + g;
                af[mi][0] = As[row * LDW + k0];
                af[mi][1] = As[(row + 8) * LDW + k0];
                af[mi][2] = As[row * LDW + k0 + 4];
                af[mi][3] = As[(row + 8) * LDW + k0 + 4];
            }
            #pragma unroll
            for (int nj = 0; nj < 8; nj++) {
                const int col = wn + nj * 8 + g;
                uint32_t b0 = Bs[col * LDW + k0];
                uint32_t b1 = Bs[col * LDW + k0 + 4];
                #pragma unroll
                for (int mi = 0; mi < 2; mi++)
                    MMA_TF32(acc[mi][nj][0], acc[mi][nj][1],
                             acc[mi][nj][2], acc[mi][nj][3],
                             af[mi][0], af[mi][1], af[mi][2], af[mi][3],
                             b0, b1);
            }
        }
        __syncthreads();
    }

    #pragma unroll
    for (int mi = 0; mi < 2; mi++) {
        const int row = m0 + wm + mi * 16 + g;
        #pragma unroll
        for (int nj = 0; nj < 8; nj++) {
            const int col = n0 + wn + nj * 8 + kq * 2;
            const float bx = bias[col], by = bias[col + 1];
            float2 v0 = make_float2(acc[mi][nj][0] + bx, acc[mi][nj][1] + by);
            float2 v1 = make_float2(acc[mi][nj][2] + bx, acc[mi][nj][3] + by);
            *(float2*)(C + (size_t)row * DM + col)       = v0;
            *(float2*)(C + (size_t)(row + 8) * DM + col) = v1;
        }
    }
}

// ---------------------------------------------------------------------------
// Tensor-core flash attention (tf32 mma.sync).
// CTA: (b,h) x 128 q rows. 8 warps; warp w owns q rows [w*16, w*16+16).
// Loop over 32 chunks of 64 keys.
//   Ks [64 keys][68]  : K chunk, k-major (B-frags for S)
//   Vt [64 d   ][68]  : V chunk transposed (B-frags for PV)
//   Ps [128 q  ][68]  : Q staging (prologue), then P tiles (A-frags for PV)
// All fragment reads bank-conflict-free via pad-68 (bank = 4g+kq pattern).
// ---------------------------------------------------------------------------
#define AST 68                      // padded row stride (words)
#define ATT_SMEM ((4352*2 + 64 + 8704) * 4)   // Ks+Vt+madd+Ps = 69888 B

__global__ __launch_bounds__(256, 2) void attn_mma_k(
    const float* __restrict__ q, const float* __restrict__ k,
    const float* __restrict__ v, const int* __restrict__ mask,
    float* __restrict__ o)
{
    extern __shared__ uint32_t smu[];
    uint32_t* Ks   = smu;                 // [64][68]
    uint32_t* Vt   = smu + 4352;          // [64][68]
    float*    madd = (float*)(smu + 8704);// [64]
    uint32_t* Ps   = smu + 8768;          // [128][68]

    const int t    = threadIdx.x;
    const int lane = t & 31;
    const int wid  = t >> 5;
    const int g    = lane >> 2;
    const int kq   = lane & 3;
    const int bh   = blockIdx.x;
    const int b    = bh >> 4;
    const int h    = bh & 15;
    const int qt   = blockIdx.y;

    const int qbase = b * SEQ + qt * 128;
    const int kbase = b * SEQ;
    const int hcol  = h * HD;
    const int wr    = wid * 16;

    // ---- Stage Q tile (scaled by 1/8, tf32) into Ps, pull A-fragments ----
    #pragma unroll
    for (int it = 0; it < 8; it++) {
        int idx = it * 256 + t;
        int r = idx >> 4, c4 = (idx & 15) << 2;
        float4 qv = *(const float4*)(q + (size_t)(qbase + r) * DM + hcol + c4);
        uint32_t* p = &Ps[r * AST + c4];
        p[0] = tf32r(qv.x * 0.125f); p[1] = tf32r(qv.y * 0.125f);
        p[2] = tf32r(qv.z * 0.125f); p[3] = tf32r(qv.w * 0.125f);
    }
    __syncthreads();

    uint32_t qf[8][4];
    #pragma unroll
    for (int ks = 0; ks < 8; ks++) {
        const int k0 = ks * 8 + kq;
        qf[ks][0] = Ps[(wr + g) * AST + k0];
        qf[ks][1] = Ps[(wr + g + 8) * AST + k0];
        qf[ks][2] = Ps[(wr + g) * AST + k0 + 4];
        qf[ks][3] = Ps[(wr + g + 8) * AST + k0 + 4];
    }

    float m0 = -1e30f, m1 = -1e30f, l0 = 0.f, l1 = 0.f;
    float acc[8][4];
    #pragma unroll
    for (int nt = 0; nt < 8; nt++)
        #pragma unroll
        for (int j = 0; j < 4; j++) acc[nt][j] = 0.f;

    // V transpose-load mapping (conflict-free STS, coalesced-in-8 LDG)
    const int vd = (lane & 7) + 8 * wid;     // d column this thread handles
    const int vr = lane >> 3;                // base key row (stride 4 per iter)
    const float* vbase = v + (size_t)(kbase + vr) * DM + hcol + vd;

    #pragma unroll 1
    for (int kt = 0; kt < 32; kt++) {
        __syncthreads();   // prior chunk's Ks/Vt reads done (and Q-frag reads)

        // Load K chunk (k-major, tf32)
        #pragma unroll
        for (int it = 0; it < 4; it++) {
            int idx = it * 256 + t;
            int r = idx >> 4, c4 = (idx & 15) << 2;
            float4 kv = *(const float4*)(k + (size_t)(kbase + kt * 64 + r) * DM + hcol + c4);
            uint32_t* kp = &Ks[r * AST + c4];
            kp[0] = tf32r(kv.x); kp[1] = tf32r(kv.y);
            kp[2] = tf32r(kv.z); kp[3] = tf32r(kv.w);
        }
        // Load V chunk transposed: Vt[d][key]
        {
            const float* vp = vbase + (size_t)(kt * 64) * DM;
            #pragma unroll
            for (int it = 0; it < 16; it++)
                Vt[vd * AST + vr + it * 4] = tf32r(vp[(size_t)(it * 4) * DM]);
        }
        // Mask additive
        if (t < 64)
            madd[t] = mask[b * SEQ + kt * 64 + t] ? 0.f : -1e9f;
        __syncthreads();

        // ---- S = (Q/8) K^T : 8 n-tiles x 8 k-steps ----
        float s[8][4];
        #pragma unroll
        for (int nt = 0; nt < 8; nt++)
            #pragma unroll
            for (int j = 0; j < 4; j++) s[nt][j] = 0.f;

        #pragma unroll
        for (int ks = 0; ks < 8; ks++) {
            const int k0 = ks * 8 + kq;
            #pragma unroll
            for (int nt = 0; nt < 8; nt++) {
                uint32_t b0 = Ks[(nt * 8 + g) * AST + k0];
                uint32_t b1 = Ks[(nt * 8 + g) * AST + k0 + 4];
                MMA_TF32(s[nt][0], s[nt][1], s[nt][2], s[nt][3],
                         qf[ks][0], qf[ks][1], qf[ks][2], qf[ks][3], b0, b1);
            }
        }

        // ---- Online softmax (rows g and g+8, cols all in-warp) ----
        float rmax0 = -1e30f, rmax1 = -1e30f;
        #pragma unroll
        for (int nt = 0; nt < 8; nt++) {
            float2 md = *(float2*)&madd[nt * 8 + 2 * kq];
            s[nt][0] += md.x; s[nt][1] += md.y;
            s[nt][2] += md.x; s[nt][3] += md.y;
            rmax0 = fmaxf(rmax0, fmaxf(s[nt][0], s[nt][1]));
            rmax1 = fmaxf(rmax1, fmaxf(s[nt][2], s[nt][3]));
        }
        rmax0 = fmaxf(rmax0, __shfl_xor_sync(0xffffffffu, rmax0, 1));
        rmax0 = fmaxf(rmax0, __shfl_xor_sync(0xffffffffu, rmax0, 2));
        rmax1 = fmaxf(rmax1, __shfl_xor_sync(0xffffffffu, rmax1, 1));
        rmax1 = fmaxf(rmax1, __shfl_xor_sync(0xffffffffu, rmax1, 2));

        const float mn0 = fmaxf(m0, rmax0);
        const float mn1 = fmaxf(m1, rmax1);
        const float a0  = __expf(m0 - mn0);
        const float a1  = __expf(m1 - mn1);
        float sum0 = 0.f, sum1 = 0.f;

        #pragma unroll
        for (int nt = 0; nt < 8; nt++) {
            float p0 = __expf(s[nt][0] - mn0);
            float p1 = __expf(s[nt][1] - mn0);
            float p2 = __expf(s[nt][2] - mn1);
            float p3 = __expf(s[nt][3] - mn1);
            sum0 += p0 + p1;
            sum1 += p2 + p3;
            uint2 w0 = make_uint2(tf32r(p0), tf32r(p1));
            uint2 w1 = make_uint2(tf32r(p2), tf32r(p3));
            *(uint2*)&Ps[(wr + g) * AST + nt * 8 + 2 * kq]     = w0;
            *(uint2*)&Ps[(wr + g + 8) * AST + nt * 8 + 2 * kq] = w1;
        }
        sum0 += __shfl_xor_sync(0xffffffffu, sum0, 1);
        sum0 += __shfl_xor_sync(0xffffffffu, sum0, 2);
        sum1 += __shfl_xor_sync(0xffffffffu, sum1, 1);
        sum1 += __shfl_xor_sync(0xffffffffu, sum1, 2);

        l0 = l0 * a0 + sum0;  m0 = mn0;
        l1 = l1 * a1 + sum1;  m1 = mn1;
        #pragma unroll
        for (int nt = 0; nt < 8; nt++) {
            acc[nt][0] *= a0; acc[nt][1] *= a0;
            acc[nt][2] *= a1; acc[nt][3] *= a1;
        }
        __syncwarp();   // P stores visible to own-warp LDS

        // ---- O += P V : A from Ps (own rows), B from Vt ----
        #pragma unroll
        for (int ks = 0; ks < 8; ks++) {
            const int k0 = ks * 8 + kq;
            uint32_t pa0 = Ps[(wr + g) * AST + k0];
            uint32_t pa1 = Ps[(wr + g + 8) * AST + k0];
            uint32_t pa2 = Ps[(wr + g) * AST + k0 + 4];
            uint32_t pa3 = Ps[(wr + g + 8) * AST + k0 + 4];
            #pragma unroll
            for (int nt = 0; nt < 8; nt++) {
                uint32_t b0 = Vt[(nt * 8 + g) * AST + k0];
                uint32_t b1 = Vt[(nt * 8 + g) * AST + k0 + 4];
                MMA_TF32(acc[nt][0], acc[nt][1], acc[nt][2], acc[nt][3],
                         pa0, pa1, pa2, pa3, b0, b1);
            }
        }
    }

    // ---- Finalize ----
    const float inv0 = (l0 > 0.f) ? 1.f / l0 : 0.f;
    const float inv1 = (l1 > 0.f) ? 1.f / l1 : 0.f;
    const int row0 = qbase + wr + g;
    #pragma unroll
    for (int nt = 0; nt < 8; nt++) {
        const int col = hcol + nt * 8 + 2 * kq;
        float2 o0 = make_float2(acc[nt][0] * inv0, acc[nt][1] * inv0);
        float2 o1 = make_float2(acc[nt][2] * inv1, acc[nt][3] * inv1);
        *(float2*)(o + (size_t)row0 * DM + col)       = o0;
        *(float2*)(o + (size_t)(row0 + 8) * DM + col) = o1;
    }
}

// ---------------------------------------------------------------------------
// Launch
// ---------------------------------------------------------------------------
extern "C" void kernel_launch(void* const* d_in, const int* in_sizes, int n_in,
                              void* d_out, int out_size)
{
    const float* Q    = (const float*)d_in[0];
    const float* K    = (const float*)d_in[1];
    const float* V    = (const float*)d_in[2];
    const int*   mask = (const int*)  d_in[3];
    const float* Wq   = (const float*)d_in[4];
    const float* bq   = (const float*)d_in[5];
    const float* Wk   = (const float*)d_in[6];
    const float* bk   = (const float*)d_in[7];
    const float* Wv   = (const float*)d_in[8];
    const float* bv   = (const float*)d_in[9];
    const float* Wo   = (const float*)d_in[10];
    const float* bo   = (const float*)d_in[11];
    float* out = (float*)d_out;

    float *gq, *gk, *gv, *ga, *gwt;
    cudaGetSymbolAddress((void**)&gq,  g_q);
    cudaGetSymbolAddress((void**)&gk,  g_k);
    cudaGetSymbolAddress((void**)&gv,  g_v);
    cudaGetSymbolAddress((void**)&ga,  g_att);
    cudaGetSymbolAddress((void**)&gwt, g_wt);
    float* wtq = gwt + 0 * (size_t)DM * DM;
    float* wtk = gwt + 1 * (size_t)DM * DM;
    float* wtv = gwt + 2 * (size_t)DM * DM;
    float* wto = gwt + 3 * (size_t)DM * DM;

    cudaFuncSetAttribute(attn_mma_k, cudaFuncAttributeMaxDynamicSharedMemorySize,
                         ATT_SMEM);

    dim3 tgrid(DM / 32, DM / 32);
    dim3 tblk(32, 8);
    transpose_k<<<tgrid, tblk>>>(Wq, wtq);
    transpose_k<<<tgrid, tblk>>>(Wk, wtk);
    transpose_k<<<tgrid, tblk>>>(Wv, wtv);
    transpose_k<<<tgrid, tblk>>>(Wo, wto);

    dim3 gemm_grid(DM / 128, MROWS / 128);   // (8, 64)
    dim3 attn_grid(NB * NH, SEQ / 128);      // (64, 16)

    gemm_mma_k<<<gemm_grid, 256>>>(Q, wtq, bq, gq);
    gemm_mma_k<<<gemm_grid, 256>>>(K, wtk, bk, gk);
    gemm_mma_k<<<gemm_grid, 256>>>(V, wtv, bv, gv);
    attn_mma_k<<<attn_grid, 256, ATT_SMEM>>>(gq, gk, gv, mask, ga);
    gemm_mma_k<<<gemm_grid, 256>>>(ga, wto, bo, out);
}

// round 5
// speedup vs baseline: 3.4173x; 1.0981x over previous
#include <cuda_runtime.h>
#include <math.h>
#include <stdint.h>

// Problem constants
#define NB   4
#define SEQ  2048
#define DM   1024
#define NH   16
#define HD   64
#define MROWS (NB*SEQ)          // 8192

// Scratch (device globals — no allocation allowed)
__device__ float g_q  [MROWS*DM];
__device__ float g_k  [MROWS*DM];
__device__ float g_v  [MROWS*DM];
__device__ float g_att[MROWS*DM];
__device__ float g_wt [4][DM*DM];   // transposed weights Wt[n][k] = W[k][n]

__device__ __forceinline__ uint32_t tf32r(float x) {
    uint32_t u;
    asm("cvt.rna.tf32.f32 %0, %1;" : "=r"(u) : "f"(x));
    return u;
}

__device__ __forceinline__ uint32_t smem_u32(const void* p) {
    uint32_t a;
    asm("{ .reg .u64 t; cvta.to.shared.u64 t, %1; cvt.u32.u64 %0, t; }"
        : "=r"(a) : "l"(p));
    return a;
}

#define CP_ASYNC16(dst, src) \
    asm volatile("cp.async.cg.shared.global [%0], [%1], 16;" \
                 :: "r"(dst), "l"(src) : "memory")
#define CP_COMMIT() asm volatile("cp.async.commit_group;" ::: "memory")
#define CP_WAIT0()  asm volatile("cp.async.wait_group 0;" ::: "memory")

#define MMA_TF32(c0, c1, c2, c3, a0, a1, a2, a3, b0, b1) \
    asm volatile("mma.sync.aligned.m16n8k8.row.col.f32.tf32.tf32.f32 " \
        "{%0,%1,%2,%3}, {%4,%5,%6,%7}, {%8,%9}, {%0,%1,%2,%3};" \
        : "+f"(c0), "+f"(c1), "+f"(c2), "+f"(c3) \
        : "r"(a0), "r"(a1), "r"(a2), "r"(a3), "r"(b0), "r"(b1))

// ---------------------------------------------------------------------------
// Weight transpose: D[n*1024+k] = S[k*1024+n]
// ---------------------------------------------------------------------------
__global__ __launch_bounds__(256) void transpose_k(
    const float* __restrict__ S, float* __restrict__ D)
{
    __shared__ float tile[32][33];
    const int tx = threadIdx.x, ty = threadIdx.y;
    const int x = blockIdx.x * 32 + tx;
    #pragma unroll
    for (int j = ty; j < 32; j += 8)
        tile[j][tx] = S[(size_t)(blockIdx.y * 32 + j) * DM + x];
    __syncthreads();
    const int x2 = blockIdx.y * 32 + tx;
    #pragma unroll
    for (int j = ty; j < 32; j += 8)
        D[(size_t)(blockIdx.x * 32 + j) * DM + x2] = tile[tx][j];
}

// ---------------------------------------------------------------------------
// Tensor-core GEMM via mma.sync (tf32). Fused: blockIdx.z selects which of up
// to 3 (A, Wt, bias, C) problem instances this CTA works on.
// ---------------------------------------------------------------------------
#define LDW 36   // padded row stride in words

__global__ __launch_bounds__(256) void gemm_mma_k(
    const float* __restrict__ A0, const float* __restrict__ A1,
    const float* __restrict__ A2,
    const float* __restrict__ W0, const float* __restrict__ W1,
    const float* __restrict__ W2,
    const float* __restrict__ b0_, const float* __restrict__ b1_,
    const float* __restrict__ b2_,
    float* __restrict__ C0, float* __restrict__ C1, float* __restrict__ C2)
{
    __shared__ uint32_t As[128 * LDW];
    __shared__ uint32_t Bs[128 * LDW];

    const int z = blockIdx.z;
    const float* A    = (z == 0) ? A0 : (z == 1) ? A1 : A2;
    const float* Wt   = (z == 0) ? W0 : (z == 1) ? W1 : W2;
    const float* bias = (z == 0) ? b0_ : (z == 1) ? b1_ : b2_;
    float*       C    = (z == 0) ? C0 : (z == 1) ? C1 : C2;

    const int t    = threadIdx.x;
    const int lane = t & 31;
    const int wid  = t >> 5;
    const int m0   = blockIdx.y * 128;
    const int n0   = blockIdx.x * 128;
    const int wm   = (wid & 3) * 32;
    const int wn   = (wid >> 2) * 64;
    const int g    = lane >> 2;
    const int kq   = lane & 3;

    const int lr  = t >> 3;
    const int lc4 = (t & 7) << 2;

    float acc[2][8][4];
    #pragma unroll
    for (int mi = 0; mi < 2; mi++)
        #pragma unroll
        for (int nj = 0; nj < 8; nj++)
            #pragma unroll
            for (int r = 0; r < 4; r++) acc[mi][nj][r] = 0.f;

    float4 pa[4], pb[4];

    #pragma unroll
    for (int i = 0; i < 4; i++) {
        pa[i] = *(const float4*)(A  + (size_t)(m0 + lr + i * 32) * DM + lc4);
        pb[i] = *(const float4*)(Wt + (size_t)(n0 + lr + i * 32) * DM + lc4);
    }

    #pragma unroll 1
    for (int kt = 0; kt < 32; kt++) {
        #pragma unroll
        for (int i = 0; i < 4; i++) {
            uint32_t* ap = &As[(lr + i * 32) * LDW + lc4];
            uint32_t* bp = &Bs[(lr + i * 32) * LDW + lc4];
            ap[0] = tf32r(pa[i].x); ap[1] = tf32r(pa[i].y);
            ap[2] = tf32r(pa[i].z); ap[3] = tf32r(pa[i].w);
            bp[0] = tf32r(pb[i].x); bp[1] = tf32r(pb[i].y);
            bp[2] = tf32r(pb[i].z); bp[3] = tf32r(pb[i].w);
        }
        __syncthreads();

        if (kt + 1 < 32) {
            const int kf = (kt + 1) * 32 + lc4;
            #pragma unroll
            for (int i = 0; i < 4; i++) {
                pa[i] = *(const float4*)(A  + (size_t)(m0 + lr + i * 32) * DM + kf);
                pb[i] = *(const float4*)(Wt + (size_t)(n0 + lr + i * 32) * DM + kf);
            }
        }

        #pragma unroll
        for (int ks = 0; ks < 4; ks++) {
            const int k0 = ks * 8 + kq;
            uint32_t af[2][4];
            #pragma unroll
            for (int mi = 0; mi < 2; mi++) {
                const int row = wm + mi * 16 + g;
                af[mi][0] = As[row * LDW + k0];
                af[mi][1] = As[(row + 8) * LDW + k0];
                af[mi][2] = As[row * LDW + k0 + 4];
                af[mi][3] = As[(row + 8) * LDW + k0 + 4];
            }
            #pragma unroll
            for (int nj = 0; nj < 8; nj++) {
                const int col = wn + nj * 8 + g;
                uint32_t bb0 = Bs[col * LDW + k0];
                uint32_t bb1 = Bs[col * LDW + k0 + 4];
                #pragma unroll
                for (int mi = 0; mi < 2; mi++)
                    MMA_TF32(acc[mi][nj][0], acc[mi][nj][1],
                             acc[mi][nj][2], acc[mi][nj][3],
                             af[mi][0], af[mi][1], af[mi][2], af[mi][3],
                             bb0, bb1);
            }
        }
        __syncthreads();
    }

    #pragma unroll
    for (int mi = 0; mi < 2; mi++) {
        const int row = m0 + wm + mi * 16 + g;
        #pragma unroll
        for (int nj = 0; nj < 8; nj++) {
            const int col = n0 + wn + nj * 8 + kq * 2;
            const float bx = bias[col], by = bias[col + 1];
            float2 v0 = make_float2(acc[mi][nj][0] + bx, acc[mi][nj][1] + by);
            float2 v1 = make_float2(acc[mi][nj][2] + bx, acc[mi][nj][3] + by);
            *(float2*)(C + (size_t)row * DM + col)       = v0;
            *(float2*)(C + (size_t)(row + 8) * DM + col) = v1;
        }
    }
}

// ---------------------------------------------------------------------------
// Tensor-core flash attention (tf32 mma.sync) with cp.async double buffering.
// CTA: (b,h) x 128 q rows. 8 warps; warp w owns q rows [w*16, w*16+16).
// 32 chunks of 64 keys; K,V for chunk k+1 stream in via cp.async while chunk
// k computes. One __syncthreads per chunk.
//   Ks[2][64][68] : K chunk natural [key][d]  (S B-frags: bank 4g+kq, CF)
//   Vs[2][64][72] : V chunk natural [key][d]  (PV B-frags: bank 8kq+g, CF)
//   madd[2][64]   : additive mask
//   Ps [128][68]  : Q staging (prologue) then P tiles (PV A-frags)
// ---------------------------------------------------------------------------
#define KST 68
#define VST 72
#define OFF_KS(buf) ((buf) * 4352)
#define OFF_VS(buf) (8704 + (buf) * 4608)
#define OFF_MADD(buf) (17920 + (buf) * 64)
#define OFF_PS 18048
#define ATT_WORDS (OFF_PS + 128 * KST)        // 26752 words
#define ATT_SMEM  (ATT_WORDS * 4)             // 107008 B

__global__ __launch_bounds__(256, 2) void attn_mma_k(
    const float* __restrict__ q, const float* __restrict__ k,
    const float* __restrict__ v, const int* __restrict__ mask,
    float* __restrict__ o)
{
    extern __shared__ uint32_t smu[];
    uint32_t* Ps = smu + OFF_PS;
    const uint32_t sbase = smem_u32(smu);

    const int t    = threadIdx.x;
    const int lane = t & 31;
    const int wid  = t >> 5;
    const int g    = lane >> 2;
    const int kq   = lane & 3;
    const int bh   = blockIdx.x;
    const int b    = bh >> 4;
    const int h    = bh & 15;
    const int qt   = blockIdx.y;

    const int qbase = b * SEQ + qt * 128;
    const int kbase = b * SEQ;
    const int hcol  = h * HD;
    const int wr    = wid * 16;

    // cp.async tile addressing: idx = it*256+t -> row = idx>>4, c4 = (idx&15)*4
    const int crow = t >> 4;            // row for it=0 (stride 16 rows per it)
    const int cc4  = (t & 15) << 2;

    // ---- Stage Q tile (scaled by 1/8, tf32-rounded) into Ps ----
    #pragma unroll
    for (int it = 0; it < 8; it++) {
        int idx = it * 256 + t;
        int r = idx >> 4, c4 = (idx & 15) << 2;
        float4 qv = *(const float4*)(q + (size_t)(qbase + r) * DM + hcol + c4);
        uint32_t* p = &Ps[r * KST + c4];
        p[0] = tf32r(qv.x * 0.125f); p[1] = tf32r(qv.y * 0.125f);
        p[2] = tf32r(qv.z * 0.125f); p[3] = tf32r(qv.w * 0.125f);
    }

    // ---- Issue cp.async for chunk 0 ----
    {
        const float* kp = k + (size_t)(kbase + crow) * DM + hcol + cc4;
        const float* vp = v + (size_t)(kbase + crow) * DM + hcol + cc4;
        #pragma unroll
        for (int it = 0; it < 4; it++) {
            const int r = crow + it * 16;
            CP_ASYNC16(sbase + (OFF_KS(0) + r * KST + cc4) * 4, kp + (size_t)(it * 16) * DM);
            CP_ASYNC16(sbase + (OFF_VS(0) + r * VST + cc4) * 4, vp + (size_t)(it * 16) * DM);
        }
        CP_COMMIT();
    }
    // mask chunk 0 -> madd[0]; stage chunk 1 in mreg
    if (t < 64) {
        ((float*)(smu + OFF_MADD(0)))[t] = mask[b * SEQ + t] ? 0.f : -1e9f;
    }
    int mreg = (t < 64) ? mask[b * SEQ + 64 + t] : 0;

    __syncthreads();   // Q staging visible

    // Pull Q A-fragments (held in registers for the whole loop)
    uint32_t qf[8][4];
    #pragma unroll
    for (int ks = 0; ks < 8; ks++) {
        const int k0 = ks * 8 + kq;
        qf[ks][0] = Ps[(wr + g) * KST + k0];
        qf[ks][1] = Ps[(wr + g + 8) * KST + k0];
        qf[ks][2] = Ps[(wr + g) * KST + k0 + 4];
        qf[ks][3] = Ps[(wr + g + 8) * KST + k0 + 4];
    }

    float m0 = -1e30f, m1 = -1e30f, l0 = 0.f, l1 = 0.f;
    float acc[8][4];
    #pragma unroll
    for (int nt = 0; nt < 8; nt++)
        #pragma unroll
        for (int j = 0; j < 4; j++) acc[nt][j] = 0.f;

    #pragma unroll 1
    for (int kt = 0; kt < 32; kt++) {
        const int cur = kt & 1;
        const int nxt = cur ^ 1;

        CP_WAIT0();        // chunk kt data landed
        __syncthreads();   // all warps done with nxt buffers (chunk kt-1) + cur ready

        // Issue cp.async for chunk kt+1 into nxt
        if (kt + 1 < 32) {
            const size_t rb = (size_t)(kbase + (kt + 1) * 64 + crow) * DM + hcol + cc4;
            const float* kp = k + rb;
            const float* vp = v + rb;
            #pragma unroll
            for (int it = 0; it < 4; it++) {
                const int r = crow + it * 16;
                CP_ASYNC16(sbase + (OFF_KS(nxt) + r * KST + cc4) * 4, kp + (size_t)(it * 16) * DM);
                CP_ASYNC16(sbase + (OFF_VS(nxt) + r * VST + cc4) * 4, vp + (size_t)(it * 16) * DM);
            }
            CP_COMMIT();
            // mask staging: store chunk kt+1, prefetch chunk kt+2
            if (t < 64) {
                ((float*)(smu + OFF_MADD(nxt)))[t] = mreg ? 0.f : -1e9f;
                if (kt + 2 < 32) mreg = mask[b * SEQ + (kt + 2) * 64 + t];
            }
        }

        const uint32_t* Ks = smu + OFF_KS(cur);
        const uint32_t* Vs = smu + OFF_VS(cur);
        const float* madd  = (const float*)(smu + OFF_MADD(cur));

        // ---- S = (Q/8) K^T : 8 n-tiles x 8 k-steps ----
        float s[8][4];
        #pragma unroll
        for (int nt = 0; nt < 8; nt++)
            #pragma unroll
            for (int j = 0; j < 4; j++) s[nt][j] = 0.f;

        #pragma unroll
        for (int ks = 0; ks < 8; ks++) {
            const int k0 = ks * 8 + kq;
            #pragma unroll
            for (int nt = 0; nt < 8; nt++) {
                uint32_t bb0 = Ks[(nt * 8 + g) * KST + k0];
                uint32_t bb1 = Ks[(nt * 8 + g) * KST + k0 + 4];
                MMA_TF32(s[nt][0], s[nt][1], s[nt][2], s[nt][3],
                         qf[ks][0], qf[ks][1], qf[ks][2], qf[ks][3], bb0, bb1);
            }
        }

        // ---- Online softmax (rows g and g+8; cols in-warp) ----
        float rmax0 = -1e30f, rmax1 = -1e30f;
        #pragma unroll
        for (int nt = 0; nt < 8; nt++) {
            float2 md = *(float2*)&madd[nt * 8 + 2 * kq];
            s[nt][0] += md.x; s[nt][1] += md.y;
            s[nt][2] += md.x; s[nt][3] += md.y;
            rmax0 = fmaxf(rmax0, fmaxf(s[nt][0], s[nt][1]));
            rmax1 = fmaxf(rmax1, fmaxf(s[nt][2], s[nt][3]));
        }
        rmax0 = fmaxf(rmax0, __shfl_xor_sync(0xffffffffu, rmax0, 1));
        rmax0 = fmaxf(rmax0, __shfl_xor_sync(0xffffffffu, rmax0, 2));
        rmax1 = fmaxf(rmax1, __shfl_xor_sync(0xffffffffu, rmax1, 1));
        rmax1 = fmaxf(rmax1, __shfl_xor_sync(0xffffffffu, rmax1, 2));

        const float mn0 = fmaxf(m0, rmax0);
        const float mn1 = fmaxf(m1, rmax1);
        const float a0  = __expf(m0 - mn0);
        const float a1  = __expf(m1 - mn1);
        float sum0 = 0.f, sum1 = 0.f;

        #pragma unroll
        for (int nt = 0; nt < 8; nt++) {
            float p0 = __expf(s[nt][0] - mn0);
            float p1 = __expf(s[nt][1] - mn0);
            float p2 = __expf(s[nt][2] - mn1);
            float p3 = __expf(s[nt][3] - mn1);
            sum0 += p0 + p1;
            sum1 += p2 + p3;
            uint2 w0 = make_uint2(tf32r(p0), tf32r(p1));
            uint2 w1 = make_uint2(tf32r(p2), tf32r(p3));
            *(uint2*)&Ps[(wr + g) * KST + nt * 8 + 2 * kq]     = w0;
            *(uint2*)&Ps[(wr + g + 8) * KST + nt * 8 + 2 * kq] = w1;
        }
        sum0 += __shfl_xor_sync(0xffffffffu, sum0, 1);
        sum0 += __shfl_xor_sync(0xffffffffu, sum0, 2);
        sum1 += __shfl_xor_sync(0xffffffffu, sum1, 1);
        sum1 += __shfl_xor_sync(0xffffffffu, sum1, 2);

        l0 = l0 * a0 + sum0;  m0 = mn0;
        l1 = l1 * a1 + sum1;  m1 = mn1;
        #pragma unroll
        for (int nt = 0; nt < 8; nt++) {
            acc[nt][0] *= a0; acc[nt][1] *= a0;
            acc[nt][2] *= a1; acc[nt][3] *= a1;
        }
        __syncwarp();   // P stores visible to own-warp LDS

        // ---- O += P V : A from Ps (own rows), B from Vs (natural layout) ----
        #pragma unroll
        for (int ks = 0; ks < 8; ks++) {
            const int k0 = ks * 8 + kq;
            uint32_t pa0 = Ps[(wr + g) * KST + k0];
            uint32_t pa1 = Ps[(wr + g + 8) * KST + k0];
            uint32_t pa2 = Ps[(wr + g) * KST + k0 + 4];
            uint32_t pa3 = Ps[(wr + g + 8) * KST + k0 + 4];
            #pragma unroll
            for (int nt = 0; nt < 8; nt++) {
                uint32_t bb0 = Vs[(k0) * VST + nt * 8 + g];
                uint32_t bb1 = Vs[(k0 + 4) * VST + nt * 8 + g];
                MMA_TF32(acc[nt][0], acc[nt][1], acc[nt][2], acc[nt][3],
                         pa0, pa1, pa2, pa3, bb0, bb1);
            }
        }
    }

    // ---- Finalize ----
    const float inv0 = (l0 > 0.f) ? 1.f / l0 : 0.f;
    const float inv1 = (l1 > 0.f) ? 1.f / l1 : 0.f;
    const int row0 = qbase + wr + g;
    #pragma unroll
    for (int nt = 0; nt < 8; nt++) {
        const int col = hcol + nt * 8 + 2 * kq;
        float2 o0 = make_float2(acc[nt][0] * inv0, acc[nt][1] * inv0);
        float2 o1 = make_float2(acc[nt][2] * inv1, acc[nt][3] * inv1);
        *(float2*)(o + (size_t)row0 * DM + col)       = o0;
        *(float2*)(o + (size_t)(row0 + 8) * DM + col) = o1;
    }
}

// ---------------------------------------------------------------------------
// Launch
// ---------------------------------------------------------------------------
extern "C" void kernel_launch(void* const* d_in, const int* in_sizes, int n_in,
                              void* d_out, int out_size)
{
    const float* Q    = (const float*)d_in[0];
    const float* K    = (const float*)d_in[1];
    const float* V    = (const float*)d_in[2];
    const int*   mask = (const int*)  d_in[3];
    const float* Wq   = (const float*)d_in[4];
    const float* bq   = (const float*)d_in[5];
    const float* Wk   = (const float*)d_in[6];
    const float* bk   = (const float*)d_in[7];
    const float* Wv   = (const float*)d_in[8];
    const float* bv   = (const float*)d_in[9];
    const float* Wo   = (const float*)d_in[10];
    const float* bo   = (const float*)d_in[11];
    float* out = (float*)d_out;

    float *gq, *gk, *gv, *ga, *gwt;
    cudaGetSymbolAddress((void**)&gq,  g_q);
    cudaGetSymbolAddress((void**)&gk,  g_k);
    cudaGetSymbolAddress((void**)&gv,  g_v);
    cudaGetSymbolAddress((void**)&ga,  g_att);
    cudaGetSymbolAddress((void**)&gwt, g_wt);
    float* wtq = gwt + 0 * (size_t)DM * DM;
    float* wtk = gwt + 1 * (size_t)DM * DM;
    float* wtv = gwt + 2 * (size_t)DM * DM;
    float* wto = gwt + 3 * (size_t)DM * DM;

    cudaFuncSetAttribute(attn_mma_k, cudaFuncAttributeMaxDynamicSharedMemorySize,
                         ATT_SMEM);

    dim3 tgrid(DM / 32, DM / 32);
    dim3 tblk(32, 8);
    transpose_k<<<tgrid, tblk>>>(Wq, wtq);
    transpose_k<<<tgrid, tblk>>>(Wk, wtk);
    transpose_k<<<tgrid, tblk>>>(Wv, wtv);
    transpose_k<<<tgrid, tblk>>>(Wo, wto);

    dim3 qkv_grid(DM / 128, MROWS / 128, 3);  // (8, 64, 3)
    dim3 out_grid(DM / 128, MROWS / 128, 1);  // (8, 64, 1)
    dim3 attn_grid(NB * NH, SEQ / 128);       // (64, 16)

    gemm_mma_k<<<qkv_grid, 256>>>(Q, K, V, wtq, wtk, wtv, bq, bk, bv, gq, gk, gv);
    attn_mma_k<<<attn_grid, 256, ATT_SMEM>>>(gq, gk, gv, mask, ga);
    gemm_mma_k<<<out_grid, 256>>>(ga, ga, ga, wto, wto, wto, bo, bo, bo, out, out, out);
}

// round 7
// speedup vs baseline: 3.9146x; 1.1455x over previous
#include <cuda_runtime.h>
#include <math.h>
#include <stdint.h>

// Problem constants
#define NB   4
#define SEQ  2048
#define DM   1024
#define NH   16
#define HD   64
#define MROWS (NB*SEQ)          // 8192

// Scratch (device globals — no allocation allowed)
__device__ float g_q  [MROWS*DM];
__device__ float g_k  [MROWS*DM];
__device__ float g_v  [MROWS*DM];
__device__ float g_att[MROWS*DM];

__device__ __forceinline__ uint32_t tf32r(float x) {
    uint32_t u;
    asm("cvt.rna.tf32.f32 %0, %1;" : "=r"(u) : "f"(x));
    return u;
}

__device__ __forceinline__ uint32_t smem_u32(const void* p) {
    uint32_t a;
    asm("{ .reg .u64 t; cvta.to.shared.u64 t, %1; cvt.u32.u64 %0, t; }"
        : "=r"(a) : "l"(p));
    return a;
}

#define CP_ASYNC16(dst, src) \
    asm volatile("cp.async.cg.shared.global [%0], [%1], 16;" \
                 :: "r"(dst), "l"(src) : "memory")
#define CP_COMMIT() asm volatile("cp.async.commit_group;" ::: "memory")
#define CP_WAIT0()  asm volatile("cp.async.wait_group 0;" ::: "memory")

#define MMA_TF32(c0, c1, c2, c3, a0, a1, a2, a3, b0, b1) \
    asm volatile("mma.sync.aligned.m16n8k8.row.col.f32.tf32.tf32.f32 " \
        "{%0,%1,%2,%3}, {%4,%5,%6,%7}, {%8,%9}, {%0,%1,%2,%3};" \
        : "+f"(c0), "+f"(c1), "+f"(c2), "+f"(c3) \
        : "r"(a0), "r"(a1), "r"(a2), "r"(a3), "r"(b0), "r"(b1))

// ---------------------------------------------------------------------------
// Tensor-core GEMM via mma.sync (tf32), cp.async double-buffered, weights
// consumed in NATURAL [k][n] layout (no pre-transpose).
//   C[M,1024] = A[M,1024] @ W[1024,1024] + bias
// CTA: 128x128 tile, BK=32, 256 threads = 8 warps (4m x 2n), warp = 32x64.
//   As[2][128][36] : A chunk [m][k]   (A-frags: bank 4g+kq, CF)
//   Bs[2][32][136] : W chunk [k][n]   (B-frags: bank 8kq+g, CF)
// blockIdx.z selects one of up to 3 fused problem instances.
// ---------------------------------------------------------------------------
#define LDA 36
#define LDB 136
#define GOFF_A(buf) ((buf) * (128 * LDA))                  // words
#define GOFF_B(buf) (2 * 128 * LDA + (buf) * (32 * LDB))   // words
#define GEMM_WORDS (2 * 128 * LDA + 2 * 32 * LDB)          // 17920 words
#define GEMM_SMEM  (GEMM_WORDS * 4)                        // 71680 B

__global__ __launch_bounds__(256, 2) void gemm_mma_k(
    const float* __restrict__ A0, const float* __restrict__ A1,
    const float* __restrict__ A2,
    const float* __restrict__ W0, const float* __restrict__ W1,
    const float* __restrict__ W2,
    const float* __restrict__ b0_, const float* __restrict__ b1_,
    const float* __restrict__ b2_,
    float* __restrict__ C0, float* __restrict__ C1, float* __restrict__ C2)
{
    extern __shared__ uint32_t smg[];
    const uint32_t sbase = smem_u32(smg);

    const int z = blockIdx.z;
    const float* A    = (z == 0) ? A0 : (z == 1) ? A1 : A2;
    const float* W    = (z == 0) ? W0 : (z == 1) ? W1 : W2;
    const float* bias = (z == 0) ? b0_ : (z == 1) ? b1_ : b2_;
    float*       C    = (z == 0) ? C0 : (z == 1) ? C1 : C2;

    const int t    = threadIdx.x;
    const int lane = t & 31;
    const int wid  = t >> 5;
    const int m0   = blockIdx.y * 128;
    const int n0   = blockIdx.x * 128;
    const int wm   = (wid & 3) * 32;
    const int wn   = (wid >> 2) * 64;
    const int g    = lane >> 2;
    const int kq   = lane & 3;

    // cp.async mapping — A: row = ar + i*32 (i=0..3), cols ac4..ac4+3
    const int ar  = t >> 3;              // 0..31
    const int ac4 = (t & 7) << 2;        // 0..28
    // B: row = br + i*8 (i=0..3), cols bc4..bc4+3
    const int br  = t >> 5;              // 0..7
    const int bc4 = (t & 31) << 2;       // 0..124

    float acc[2][8][4];
    #pragma unroll
    for (int mi = 0; mi < 2; mi++)
        #pragma unroll
        for (int nj = 0; nj < 8; nj++)
            #pragma unroll
            for (int r = 0; r < 4; r++) acc[mi][nj][r] = 0.f;

    // ---- Prologue: issue chunk 0 ----
    {
        const float* ap = A + (size_t)(m0 + ar) * DM + ac4;
        #pragma unroll
        for (int i = 0; i < 4; i++)
            CP_ASYNC16(sbase + (GOFF_A(0) + (ar + i * 32) * LDA + ac4) * 4,
                       ap + (size_t)(i * 32) * DM);
        const float* wp = W + (size_t)br * DM + n0 + bc4;
        #pragma unroll
        for (int i = 0; i < 4; i++)
            CP_ASYNC16(sbase + (GOFF_B(0) + (br + i * 8) * LDB + bc4) * 4,
                       wp + (size_t)(i * 8) * DM);
        CP_COMMIT();
    }

    #pragma unroll 1
    for (int kt = 0; kt < 32; kt++) {
        const int cur = kt & 1;
        const int nxt = cur ^ 1;

        CP_WAIT0();
        __syncthreads();

        if (kt + 1 < 32) {
            const int kf = (kt + 1) * 32;
            const float* ap = A + (size_t)(m0 + ar) * DM + kf + ac4;
            #pragma unroll
            for (int i = 0; i < 4; i++)
                CP_ASYNC16(sbase + (GOFF_A(nxt) + (ar + i * 32) * LDA + ac4) * 4,
                           ap + (size_t)(i * 32) * DM);
            const float* wp = W + (size_t)(kf + br) * DM + n0 + bc4;
            #pragma unroll
            for (int i = 0; i < 4; i++)
                CP_ASYNC16(sbase + (GOFF_B(nxt) + (br + i * 8) * LDB + bc4) * 4,
                           wp + (size_t)(i * 8) * DM);
            CP_COMMIT();
        }

        const uint32_t* As = smg + GOFF_A(cur);
        const uint32_t* Bs = smg + GOFF_B(cur);

        #pragma unroll
        for (int ks = 0; ks < 4; ks++) {
            const int k0 = ks * 8 + kq;
            uint32_t af[2][4];
            #pragma unroll
            for (int mi = 0; mi < 2; mi++) {
                const int row = wm + mi * 16 + g;
                af[mi][0] = As[row * LDA + k0];
                af[mi][1] = As[(row + 8) * LDA + k0];
                af[mi][2] = As[row * LDA + k0 + 4];
                af[mi][3] = As[(row + 8) * LDA + k0 + 4];
            }
            #pragma unroll
            for (int nj = 0; nj < 8; nj++) {
                const int col = wn + nj * 8 + g;
                uint32_t bb0 = Bs[k0 * LDB + col];
                uint32_t bb1 = Bs[(k0 + 4) * LDB + col];
                #pragma unroll
                for (int mi = 0; mi < 2; mi++)
                    MMA_TF32(acc[mi][nj][0], acc[mi][nj][1],
                             acc[mi][nj][2], acc[mi][nj][3],
                             af[mi][0], af[mi][1], af[mi][2], af[mi][3],
                             bb0, bb1);
            }
        }
    }

    #pragma unroll
    for (int mi = 0; mi < 2; mi++) {
        const int row = m0 + wm + mi * 16 + g;
        #pragma unroll
        for (int nj = 0; nj < 8; nj++) {
            const int col = n0 + wn + nj * 8 + kq * 2;
            const float bx = bias[col], by = bias[col + 1];
            float2 v0 = make_float2(acc[mi][nj][0] + bx, acc[mi][nj][1] + by);
            float2 v1 = make_float2(acc[mi][nj][2] + bx, acc[mi][nj][3] + by);
            *(float2*)(C + (size_t)row * DM + col)       = v0;
            *(float2*)(C + (size_t)(row + 8) * DM + col) = v1;
        }
    }
}

// ---------------------------------------------------------------------------
// Tensor-core flash attention (tf32 mma.sync) with cp.async double buffering.
// Unchanged from R5 (passing).
// ---------------------------------------------------------------------------
#define KST 68
#define VST 72
#define OFF_KS(buf) ((buf) * 4352)
#define OFF_VS(buf) (8704 + (buf) * 4608)
#define OFF_MADD(buf) (17920 + (buf) * 64)
#define OFF_PS 18048
#define ATT_WORDS (OFF_PS + 128 * KST)        // 26752 words
#define ATT_SMEM  (ATT_WORDS * 4)             // 107008 B

__global__ __launch_bounds__(256, 2) void attn_mma_k(
    const float* __restrict__ q, const float* __restrict__ k,
    const float* __restrict__ v, const int* __restrict__ mask,
    float* __restrict__ o)
{
    extern __shared__ uint32_t smu[];
    uint32_t* Ps = smu + OFF_PS;
    const uint32_t sbase = smem_u32(smu);

    const int t    = threadIdx.x;
    const int lane = t & 31;
    const int wid  = t >> 5;
    const int g    = lane >> 2;
    const int kq   = lane & 3;
    const int bh   = blockIdx.x;
    const int b    = bh >> 4;
    const int h    = bh & 15;
    const int qt   = blockIdx.y;

    const int qbase = b * SEQ + qt * 128;
    const int kbase = b * SEQ;
    const int hcol  = h * HD;
    const int wr    = wid * 16;

    const int crow = t >> 4;
    const int cc4  = (t & 15) << 2;

    #pragma unroll
    for (int it = 0; it < 8; it++) {
        int idx = it * 256 + t;
        int r = idx >> 4, c4 = (idx & 15) << 2;
        float4 qv = *(const float4*)(q + (size_t)(qbase + r) * DM + hcol + c4);
        uint32_t* p = &Ps[r * KST + c4];
        p[0] = tf32r(qv.x * 0.125f); p[1] = tf32r(qv.y * 0.125f);
        p[2] = tf32r(qv.z * 0.125f); p[3] = tf32r(qv.w * 0.125f);
    }

    {
        const float* kp = k + (size_t)(kbase + crow) * DM + hcol + cc4;
        const float* vp = v + (size_t)(kbase + crow) * DM + hcol + cc4;
        #pragma unroll
        for (int it = 0; it < 4; it++) {
            const int r = crow + it * 16;
            CP_ASYNC16(sbase + (OFF_KS(0) + r * KST + cc4) * 4, kp + (size_t)(it * 16) * DM);
            CP_ASYNC16(sbase + (OFF_VS(0) + r * VST + cc4) * 4, vp + (size_t)(it * 16) * DM);
        }
        CP_COMMIT();
    }
    if (t < 64) {
        ((float*)(smu + OFF_MADD(0)))[t] = mask[b * SEQ + t] ? 0.f : -1e9f;
    }
    int mreg = (t < 64) ? mask[b * SEQ + 64 + t] : 0;

    __syncthreads();

    uint32_t qf[8][4];
    #pragma unroll
    for (int ks = 0; ks < 8; ks++) {
        const int k0 = ks * 8 + kq;
        qf[ks][0] = Ps[(wr + g) * KST + k0];
        qf[ks][1] = Ps[(wr + g + 8) * KST + k0];
        qf[ks][2] = Ps[(wr + g) * KST + k0 + 4];
        qf[ks][3] = Ps[(wr + g + 8) * KST + k0 + 4];
    }

    float m0 = -1e30f, m1 = -1e30f, l0 = 0.f, l1 = 0.f;
    float acc[8][4];
    #pragma unroll
    for (int nt = 0; nt < 8; nt++)
        #pragma unroll
        for (int j = 0; j < 4; j++) acc[nt][j] = 0.f;

    #pragma unroll 1
    for (int kt = 0; kt < 32; kt++) {
        const int cur = kt & 1;
        const int nxt = cur ^ 1;

        CP_WAIT0();
        __syncthreads();

        if (kt + 1 < 32) {
            const size_t rb = (size_t)(kbase + (kt + 1) * 64 + crow) * DM + hcol + cc4;
            const float* kp = k + rb;
            const float* vp = v + rb;
            #pragma unroll
            for (int it = 0; it < 4; it++) {
                const int r = crow + it * 16;
                CP_ASYNC16(sbase + (OFF_KS(nxt) + r * KST + cc4) * 4, kp + (size_t)(it * 16) * DM);
                CP_ASYNC16(sbase + (OFF_VS(nxt) + r * VST + cc4) * 4, vp + (size_t)(it * 16) * DM);
            }
            CP_COMMIT();
            if (t < 64) {
                ((float*)(smu + OFF_MADD(nxt)))[t] = mreg ? 0.f : -1e9f;
                if (kt + 2 < 32) mreg = mask[b * SEQ + (kt + 2) * 64 + t];
            }
        }

        const uint32_t* Ks = smu + OFF_KS(cur);
        const uint32_t* Vs = smu + OFF_VS(cur);
        const float* madd  = (const float*)(smu + OFF_MADD(cur));

        float s[8][4];
        #pragma unroll
        for (int nt = 0; nt < 8; nt++)
            #pragma unroll
            for (int j = 0; j < 4; j++) s[nt][j] = 0.f;

        #pragma unroll
        for (int ks = 0; ks < 8; ks++) {
            const int k0 = ks * 8 + kq;
            #pragma unroll
            for (int nt = 0; nt < 8; nt++) {
                uint32_t bb0 = Ks[(nt * 8 + g) * KST + k0];
                uint32_t bb1 = Ks[(nt * 8 + g) * KST + k0 + 4];
                MMA_TF32(s[nt][0], s[nt][1], s[nt][2], s[nt][3],
                         qf[ks][0], qf[ks][1], qf[ks][2], qf[ks][3], bb0, bb1);
            }
        }

        float rmax0 = -1e30f, rmax1 = -1e30f;
        #pragma unroll
        for (int nt = 0; nt < 8; nt++) {
            float2 md = *(float2*)&madd[nt * 8 + 2 * kq];
            s[nt][0] += md.x; s[nt][1] += md.y;
            s[nt][2] += md.x; s[nt][3] += md.y;
            rmax0 = fmaxf(rmax0, fmaxf(s[nt][0], s[nt][1]));
            rmax1 = fmaxf(rmax1, fmaxf(s[nt][2], s[nt][3]));
        }
        rmax0 = fmaxf(rmax0, __shfl_xor_sync(0xffffffffu, rmax0, 1));
        rmax0 = fmaxf(rmax0, __shfl_xor_sync(0xffffffffu, rmax0, 2));
        rmax1 = fmaxf(rmax1, __shfl_xor_sync(0xffffffffu, rmax1, 1));
        rmax1 = fmaxf(rmax1, __shfl_xor_sync(0xffffffffu, rmax1, 2));

        const float mn0 = fmaxf(m0, rmax0);
        const float mn1 = fmaxf(m1, rmax1);
        const float a0  = __expf(m0 - mn0);
        const float a1  = __expf(m1 - mn1);
        float sum0 = 0.f, sum1 = 0.f;

        #pragma unroll
        for (int nt = 0; nt < 8; nt++) {
            float p0 = __expf(s[nt][0] - mn0);
            float p1 = __expf(s[nt][1] - mn0);
            float p2 = __expf(s[nt][2] - mn1);
            float p3 = __expf(s[nt][3] - mn1);
            sum0 += p0 + p1;
            sum1 += p2 + p3;
            uint2 w0 = make_uint2(tf32r(p0), tf32r(p1));
            uint2 w1 = make_uint2(tf32r(p2), tf32r(p3));
            *(uint2*)&Ps[(wr + g) * KST + nt * 8 + 2 * kq]     = w0;
            *(uint2*)&Ps[(wr + g + 8) * KST + nt * 8 + 2 * kq] = w1;
        }
        sum0 += __shfl_xor_sync(0xffffffffu, sum0, 1);
        sum0 += __shfl_xor_sync(0xffffffffu, sum0, 2);
        sum1 += __shfl_xor_sync(0xffffffffu, sum1, 1);
        sum1 += __shfl_xor_sync(0xffffffffu, sum1, 2);

        l0 = l0 * a0 + sum0;  m0 = mn0;
        l1 = l1 * a1 + sum1;  m1 = mn1;
        #pragma unroll
        for (int nt = 0; nt < 8; nt++) {
            acc[nt][0] *= a0; acc[nt][1] *= a0;
            acc[nt][2] *= a1; acc[nt][3] *= a1;
        }
        __syncwarp();

        #pragma unroll
        for (int ks = 0; ks < 8; ks++) {
            const int k0 = ks * 8 + kq;
            uint32_t pa0 = Ps[(wr + g) * KST + k0];
            uint32_t pa1 = Ps[(wr + g + 8) * KST + k0];
            uint32_t pa2 = Ps[(wr + g) * KST + k0 + 4];
            uint32_t pa3 = Ps[(wr + g + 8) * KST + k0 + 4];
            #pragma unroll
            for (int nt = 0; nt < 8; nt++) {
                uint32_t bb0 = Vs[(k0) * VST + nt * 8 + g];
                uint32_t bb1 = Vs[(k0 + 4) * VST + nt * 8 + g];
                MMA_TF32(acc[nt][0], acc[nt][1], acc[nt][2], acc[nt][3],
                         pa0, pa1, pa2, pa3, bb0, bb1);
            }
        }
    }

    const float inv0 = (l0 > 0.f) ? 1.f / l0 : 0.f;
    const float inv1 = (l1 > 0.f) ? 1.f / l1 : 0.f;
    const int row0 = qbase + wr + g;
    #pragma unroll
    for (int nt = 0; nt < 8; nt++) {
        const int col = hcol + nt * 8 + 2 * kq;
        float2 o0 = make_float2(acc[nt][0] * inv0, acc[nt][1] * inv0);
        float2 o1 = make_float2(acc[nt][2] * inv1, acc[nt][3] * inv1);
        *(float2*)(o + (size_t)row0 * DM + col)       = o0;
        *(float2*)(o + (size_t)(row0 + 8) * DM + col) = o1;
    }
}

// ---------------------------------------------------------------------------
// Launch: QKV GEMMs fused (z=3) -> attention -> output GEMM.
// ---------------------------------------------------------------------------
extern "C" void kernel_launch(void* const* d_in, const int* in_sizes, int n_in,
                              void* d_out, int out_size)
{
    const float* Q    = (const float*)d_in[0];
    const float* K    = (const float*)d_in[1];
    const float* V    = (const float*)d_in[2];
    const int*   mask = (const int*)  d_in[3];
    const float* Wq   = (const float*)d_in[4];
    const float* bq   = (const float*)d_in[5];
    const float* Wk   = (const float*)d_in[6];
    const float* bk   = (const float*)d_in[7];
    const float* Wv   = (const float*)d_in[8];
    const float* bv   = (const float*)d_in[9];
    const float* Wo   = (const float*)d_in[10];
    const float* bo   = (const float*)d_in[11];
    float* out = (float*)d_out;

    float *gq, *gk, *gv, *ga;
    cudaGetSymbolAddress((void**)&gq,  g_q);
    cudaGetSymbolAddress((void**)&gk,  g_k);
    cudaGetSymbolAddress((void**)&gv,  g_v);
    cudaGetSymbolAddress((void**)&ga,  g_att);

    cudaFuncSetAttribute(gemm_mma_k, cudaFuncAttributeMaxDynamicSharedMemorySize,
                         GEMM_SMEM);
    cudaFuncSetAttribute(attn_mma_k, cudaFuncAttributeMaxDynamicSharedMemorySize,
                         ATT_SMEM);

    dim3 qkv_grid(DM / 128, MROWS / 128, 3);  // (8, 64, 3)
    dim3 out_grid(DM / 128, MROWS / 128, 1);  // (8, 64, 1)
    dim3 attn_grid(NB * NH, SEQ / 128);       // (64, 16)

    gemm_mma_k<<<qkv_grid, 256, GEMM_SMEM>>>(Q, K, V, Wq, Wk, Wv,
                                             bq, bk, bv, gq, gk, gv);
    attn_mma_k<<<attn_grid, 256, ATT_SMEM>>>(gq, gk, gv, mask, ga);
    gemm_mma_k<<<out_grid, 256, GEMM_SMEM>>>(ga, ga, ga, Wo, Wo, Wo,
                                             bo, bo, bo, out, out, out);
}